// round 5
// baseline (speedup 1.0000x reference)
#include <cuda_runtime.h>
#include <cuda_bf16.h>
#include <math.h>
#include <stdint.h>

#define Bb 2
#define Ll 2048
#define DMM 512
#define Hh 8
#define Dd 64
#define NUMK 40
#define NUMQ 40
#define LN_EPS 1e-5f

// ---------------- scratch (static device globals; no allocs allowed) ----------------
__device__ __align__(256) float g_qp[Bb*Ll*DMM];
__device__ __align__(256) float g_kp[Bb*Ll*DMM];
__device__ __align__(256) float g_vp[Bb*Ll*DMM];
__device__ __align__(256) float g_measure[Bb*Hh*Ll];
__device__ __align__(256) float g_vpart[Bb*64*DMM];
__device__ __align__(256) float g_vmean[Bb*DMM];
__device__ __align__(256) int   g_qidx[Bb*Hh*NUMQ];
__device__ __align__(256) int   g_slot[Bb*Hh*Ll];
__device__ __align__(256) float g_outsel[Bb*Hh*NUMQ*Dd];
// W transposed + bf16 hi/lo split: [which][N][K]
__device__ __align__(256) __nv_bfloat16 g_Wth[3*DMM*DMM];
__device__ __align__(256) __nv_bfloat16 g_Wtl[3*DMM*DMM];
// A (q,k,v) bf16 hi/lo split: [which][M][K]
__device__ __align__(256) __nv_bfloat16 g_Ah[3*Bb*Ll*DMM];
__device__ __align__(256) __nv_bfloat16 g_Al[3*Bb*Ll*DMM];

// ============================ helpers ============================
__device__ __forceinline__ uint32_t smem_u32(const void* p) {
    uint32_t a;
    asm("{ .reg .u64 t; cvta.to.shared.u64 t, %1; cvt.u32.u64 %0, t; }" : "=r"(a) : "l"(p));
    return a;
}
#define SWZ64(off) ((off) ^ (((off) >> 3) & 0x30))

__device__ __forceinline__ void cpasync16(uint32_t dst, const void* src) {
    asm volatile("cp.async.cg.shared.global [%0], [%1], 16;" :: "r"(dst), "l"(src) : "memory");
}
#define CP_COMMIT() asm volatile("cp.async.commit_group;" ::: "memory")
#define CP_WAIT1()  asm volatile("cp.async.wait_group 1;" ::: "memory")

__device__ __forceinline__ void ldsm4(uint32_t& r0, uint32_t& r1, uint32_t& r2, uint32_t& r3,
                                      uint32_t addr) {
    asm volatile("ldmatrix.sync.aligned.m8n8.x4.shared.b16 {%0,%1,%2,%3}, [%4];"
                 : "=r"(r0), "=r"(r1), "=r"(r2), "=r"(r3) : "r"(addr));
}
__device__ __forceinline__ void mma16816(float* c, const uint32_t* a, uint32_t b0, uint32_t b1) {
    asm volatile(
        "mma.sync.aligned.m16n8k16.row.col.f32.bf16.bf16.f32 "
        "{%0,%1,%2,%3}, {%4,%5,%6,%7}, {%8,%9}, {%0,%1,%2,%3};"
        : "+f"(c[0]), "+f"(c[1]), "+f"(c[2]), "+f"(c[3])
        : "r"(a[0]), "r"(a[1]), "r"(a[2]), "r"(a[3]), "r"(b0), "r"(b1));
}

// ---------------- fp32 -> (hi, lo) bf16 split for q,k,v ----------------
__global__ void asplit_kernel(const float* __restrict__ q, const float* __restrict__ k,
                              const float* __restrict__ v)
{
    int which = blockIdx.z;
    const float* src = (which == 0) ? q : (which == 1) ? k : v;
    __nv_bfloat16* hi = g_Ah + (size_t)which * (Bb*Ll*DMM);
    __nv_bfloat16* lo = g_Al + (size_t)which * (Bb*Ll*DMM);
    int i = blockIdx.x * blockDim.x + threadIdx.x;    // one float4
    float4 x = ((const float4*)src)[i];
    __nv_bfloat16 h0 = __float2bfloat16(x.x), h1 = __float2bfloat16(x.y);
    __nv_bfloat16 h2 = __float2bfloat16(x.z), h3 = __float2bfloat16(x.w);
    __nv_bfloat162 hh0(h0, h1), hh1(h2, h3);
    __nv_bfloat162 ll0(__float2bfloat16(x.x - __bfloat162float(h0)),
                       __float2bfloat16(x.y - __bfloat162float(h1)));
    __nv_bfloat162 ll1(__float2bfloat16(x.z - __bfloat162float(h2)),
                       __float2bfloat16(x.w - __bfloat162float(h3)));
    ((__nv_bfloat162*)hi)[2*i]   = hh0;
    ((__nv_bfloat162*)hi)[2*i+1] = hh1;
    ((__nv_bfloat162*)lo)[2*i]   = ll0;
    ((__nv_bfloat162*)lo)[2*i+1] = ll1;
}

// ---------------- W transpose + bf16 split: Wt[n][k] = W[k][n] ----------------
__global__ void wsplit_t_kernel(const float* __restrict__ Wq,
                                const float* __restrict__ Wk,
                                const float* __restrict__ Wv)
{
    int which = blockIdx.z;
    const float* W = (which == 0) ? Wq : (which == 1) ? Wk : Wv;
    __nv_bfloat16* Th = g_Wth + (size_t)which * DMM * DMM;
    __nv_bfloat16* Tl = g_Wtl + (size_t)which * DMM * DMM;
    __shared__ float tile[32][33];
    int n0 = blockIdx.x * 32, k0 = blockIdx.y * 32;
    int x = threadIdx.x, y = threadIdx.y;   // 32 x 8
#pragma unroll
    for (int yy = 0; yy < 32; yy += 8)
        tile[y + yy][x] = W[(size_t)(k0 + y + yy) * DMM + n0 + x];
    __syncthreads();
#pragma unroll
    for (int yy = 0; yy < 32; yy += 8) {
        int n = n0 + y + yy;
        float f = tile[x][y + yy];           // = W[k0+x][n]
        __nv_bfloat16 h = __float2bfloat16(f);
        Th[(size_t)n * DMM + k0 + x] = h;
        Tl[(size_t)n * DMM + k0 + x] = __float2bfloat16(f - __bfloat162float(h));
    }
}

// ---------------- HMMA GEMM: C[4096,512] = A @ W + bias (3-term bf16 split) ----------------
// CTA tile M=128,N=128,BK=32. 8 warps of 64x32. cp.async 3-stage pipeline, SW64 smem.
#define ST_AH 0
#define ST_AL 8192
#define ST_BH 16384
#define ST_BL 24576
#define STAGE_BYTES 32768
#define GEMM_SMEM (3*STAGE_BYTES + 1024)

__global__ void __launch_bounds__(256)
gemm_tc_kernel(const float* __restrict__ bq, const float* __restrict__ bk,
               const float* __restrict__ bv)
{
    extern __shared__ char dsm[];

    int which = blockIdx.z;
    const float* bias = (which == 0) ? bq  : (which == 1) ? bk  : bv;
    float* C          = (which == 0) ? g_qp : (which == 1) ? g_kp : g_vp;
    const __nv_bfloat16* Ah = g_Ah + (size_t)which * (Bb*Ll*DMM);
    const __nv_bfloat16* Al = g_Al + (size_t)which * (Bb*Ll*DMM);
    const __nv_bfloat16* Bh = g_Wth + (size_t)which * DMM * DMM;
    const __nv_bfloat16* Bl = g_Wtl + (size_t)which * DMM * DMM;

    int tid = threadIdx.x, wid = tid >> 5, lane = tid & 31;
    int m0 = blockIdx.y * 128, n0 = blockIdx.x * 128;
    int wm = wid & 1, wn = wid >> 1;          // warp tile: rows wm*64, cols wn*32
    int lhalf = lane >> 4;

    uint32_t sb = (smem_u32(dsm) + 1023u) & ~1023u;

    // load geometry: 512 chunks per tile, thread does chunks tid and tid+256
    int lrow[2], lc[2];
    uint32_t ldst[2];
#pragma unroll
    for (int jj = 0; jj < 2; jj++) {
        int i = tid + 256 * jj;
        lrow[jj] = i >> 2;
        lc[jj]   = i & 3;
        ldst[jj] = SWZ64((uint32_t)(lrow[jj] * 64 + lc[jj] * 16));
    }

    // ldmatrix row bases (bytes)
    uint32_t a_base[4], b_base[2];
#pragma unroll
    for (int mt = 0; mt < 4; mt++)
        a_base[mt] = (uint32_t)((wm*64 + mt*16 + (lane & 15)) * 64);
#pragma unroll
    for (int bt = 0; bt < 2; bt++)
        b_base[bt] = (uint32_t)((wn*32 + bt*16 + (lane & 15)) * 64);

    float acc[4][4][4];
#pragma unroll
    for (int i = 0; i < 4; i++)
#pragma unroll
        for (int j = 0; j < 4; j++)
#pragma unroll
            for (int c = 0; c < 4; c++) acc[i][j][c] = 0.f;

#define LOADSTAGE(s, kt)                                                        \
    do {                                                                        \
        uint32_t st_ = sb + (uint32_t)(s) * STAGE_BYTES;                        \
        int kb_ = (kt) * 32;                                                    \
        _Pragma("unroll")                                                       \
        for (int jj = 0; jj < 2; jj++) {                                        \
            size_t ga = (size_t)(m0 + lrow[jj]) * DMM + kb_ + lc[jj] * 8;       \
            size_t gb = (size_t)(n0 + lrow[jj]) * DMM + kb_ + lc[jj] * 8;       \
            cpasync16(st_ + ST_AH + ldst[jj], Ah + ga);                         \
            cpasync16(st_ + ST_AL + ldst[jj], Al + ga);                         \
            cpasync16(st_ + ST_BH + ldst[jj], Bh + gb);                         \
            cpasync16(st_ + ST_BL + ldst[jj], Bl + gb);                         \
        }                                                                       \
    } while (0)

    LOADSTAGE(0, 0); CP_COMMIT();
    LOADSTAGE(1, 1); CP_COMMIT();

    for (int kt = 0; kt < 16; kt++) {
        CP_WAIT1();
        __syncthreads();
        if (kt + 2 < 16) LOADSTAGE((kt + 2) % 3, kt + 2);
        CP_COMMIT();

        uint32_t ss = sb + (uint32_t)(kt % 3) * STAGE_BYTES;
#pragma unroll
        for (int ks = 0; ks < 2; ks++) {
            uint32_t chunk = (uint32_t)((2*ks + lhalf) * 16);
            uint32_t bhf[2][4], blf[2][4];
#pragma unroll
            for (int bt = 0; bt < 2; bt++) {
                uint32_t sw = SWZ64(b_base[bt] + chunk);
                ldsm4(bhf[bt][0], bhf[bt][1], bhf[bt][2], bhf[bt][3], ss + ST_BH + sw);
                ldsm4(blf[bt][0], blf[bt][1], blf[bt][2], blf[bt][3], ss + ST_BL + sw);
            }
            uint32_t ar[4][4];
#pragma unroll
            for (int mt = 0; mt < 4; mt++) {
                uint32_t sw = SWZ64(a_base[mt] + chunk);
                ldsm4(ar[mt][0], ar[mt][1], ar[mt][2], ar[mt][3], ss + ST_AH + sw);
            }
#pragma unroll
            for (int mt = 0; mt < 4; mt++)
#pragma unroll
                for (int nt = 0; nt < 4; nt++) {
                    int bt = nt >> 1, hi = nt & 1;
                    mma16816(acc[mt][nt], ar[mt], bhf[bt][hi], bhf[bt][hi+2]);
                    mma16816(acc[mt][nt], ar[mt], blf[bt][hi], blf[bt][hi+2]);
                }
#pragma unroll
            for (int mt = 0; mt < 4; mt++) {
                uint32_t sw = SWZ64(a_base[mt] + chunk);
                ldsm4(ar[mt][0], ar[mt][1], ar[mt][2], ar[mt][3], ss + ST_AL + sw);
            }
#pragma unroll
            for (int mt = 0; mt < 4; mt++)
#pragma unroll
                for (int nt = 0; nt < 4; nt++) {
                    int bt = nt >> 1, hi = nt & 1;
                    mma16816(acc[mt][nt], ar[mt], bhf[bt][hi], bhf[bt][hi+2]);
                }
        }
    }

    // epilogue: c0,c1 -> (row=lane>>2, col=(lane&3)*2); c2,c3 -> row+8
#pragma unroll
    for (int mt = 0; mt < 4; mt++) {
        int mrow = m0 + wm*64 + mt*16 + (lane >> 2);
#pragma unroll
        for (int nt = 0; nt < 4; nt++) {
            int ncol = n0 + wn*32 + nt*8 + (lane & 3)*2;
            float b0 = bias[ncol], b1 = bias[ncol + 1];
            float2 v0 = make_float2(acc[mt][nt][0] + b0, acc[mt][nt][1] + b1);
            float2 v1 = make_float2(acc[mt][nt][2] + b0, acc[mt][nt][3] + b1);
            *(float2*)(C + (size_t)mrow * DMM + ncol)       = v0;
            *(float2*)(C + (size_t)(mrow + 8) * DMM + ncol) = v1;
        }
    }
}

// ---------------- v_mean (two-stage, deterministic) ----------------
__global__ void vmean_part_kernel() {
    int blk = blockIdx.x;               // 128
    int b = blk >> 6, j = blk & 63;
    int c = threadIdx.x;                // 512
    float s = 0.f;
    int base = j * 32;
    for (int l = base; l < base + 32; l++) s += g_vp[((size_t)b*Ll + l)*DMM + c];
    g_vpart[(size_t)blk*DMM + c] = s;
}
__global__ void vmean_reduce_kernel() {
    int b = blockIdx.x; int c = threadIdx.x;
    float s0 = 0.f, s1 = 0.f, s2 = 0.f, s3 = 0.f;
#pragma unroll
    for (int j = 0; j < 64; j += 4) {
        s0 += g_vpart[((size_t)b*64 + j    )*DMM + c];
        s1 += g_vpart[((size_t)b*64 + j + 1)*DMM + c];
        s2 += g_vpart[((size_t)b*64 + j + 2)*DMM + c];
        s3 += g_vpart[((size_t)b*64 + j + 3)*DMM + c];
    }
    g_vmean[b*DMM + c] = ((s0 + s1) + (s2 + s3)) * (1.0f / Ll);
}

// ---------------- slot map ----------------
__global__ void slot_init_kernel() {
    int i = blockIdx.x * blockDim.x + threadIdx.x;
    g_slot[i] = -1;
}
__global__ void slot_scatter_kernel() {
    int t = blockIdx.x * blockDim.x + threadIdx.x;
    if (t >= Bb*Hh*NUMQ) return;
    int bh = t / NUMQ, s = t % NUMQ;
    g_slot[(size_t)bh * Ll + g_qidx[bh*NUMQ + s]] = s;
}

// ---------------- pre + measure: one warp per (b,l), all 8 heads ----------------
__global__ __launch_bounds__(256) void measure_kernel(const int* __restrict__ ridx) {
    int gw = (blockIdx.x * blockDim.x + threadIdx.x) >> 5;   // 0..4095
    int lane = threadIdx.x & 31;
    if (gw >= Bb * Ll) return;
    int l = gw & (Ll - 1);
    int b = gw >> 11;
    const float4* qrow = (const float4*)&g_qp[((size_t)b*Ll + l) * DMM];
    float4 q0 = qrow[lane*4+0], q1 = qrow[lane*4+1], q2 = qrow[lane*4+2], q3 = qrow[lane*4+3];
    int i0 = ridx[l*NUMK + lane];
    int i1 = ridx[l*NUMK + 32 + (lane & 7)];
    float mx = -INFINITY, sm = 0.f;
#pragma unroll 4
    for (int j = 0; j < NUMK; j++) {
        int ki = (j < 32) ? __shfl_sync(0xffffffffu, i0, j)
                          : __shfl_sync(0xffffffffu, i1, j - 32);
        const float4* kr = (const float4*)&g_kp[((size_t)b*Ll + ki) * DMM];
        float4 k0 = kr[lane*4+0], k1 = kr[lane*4+1], k2 = kr[lane*4+2], k3 = kr[lane*4+3];
        float p = q0.x*k0.x + q0.y*k0.y + q0.z*k0.z + q0.w*k0.w
                + q1.x*k1.x + q1.y*k1.y + q1.z*k1.z + q1.w*k1.w
                + q2.x*k2.x + q2.y*k2.y + q2.z*k2.z + q2.w*k2.w
                + q3.x*k3.x + q3.y*k3.y + q3.z*k3.z + q3.w*k3.w;
        p += __shfl_xor_sync(0xffffffffu, p, 1);
        p += __shfl_xor_sync(0xffffffffu, p, 2);
        mx = fmaxf(mx, p);
        sm += p;
    }
    if ((lane & 3) == 0) {
        int h = lane >> 2;
        g_measure[((size_t)b*Hh + h)*Ll + l] = mx - sm * (1.0f / Ll);
    }
}

// ---------------- exact top-40 per (b,h), register-resident ----------------
__global__ __launch_bounds__(256) void topk_kernel() {
    int bh = blockIdx.x, t = threadIdx.x;
    float v[8];
    const float* src = g_measure + (size_t)bh * Ll;
#pragma unroll
    for (int m = 0; m < 8; m++) v[m] = src[t + 256*m];
    __shared__ float swv[8];
    __shared__ int   swi[8];
    __shared__ int   s_best;
    for (int s = 0; s < NUMQ; s++) {
        float bv = v[0]; int bi = t;
#pragma unroll
        for (int m = 1; m < 8; m++) {
            int i = t + 256*m;
            if (v[m] > bv || (v[m] == bv && i < bi)) { bv = v[m]; bi = i; }
        }
#pragma unroll
        for (int o = 16; o; o >>= 1) {
            float ov = __shfl_xor_sync(0xffffffffu, bv, o);
            int   oi = __shfl_xor_sync(0xffffffffu, bi, o);
            if (ov > bv || (ov == bv && oi < bi)) { bv = ov; bi = oi; }
        }
        if ((t & 31) == 0) { swv[t >> 5] = bv; swi[t >> 5] = bi; }
        __syncthreads();
        if (t == 0) {
            float rv = swv[0]; int ri = swi[0];
#pragma unroll
            for (int w = 1; w < 8; w++)
                if (swv[w] > rv || (swv[w] == rv && swi[w] < ri)) { rv = swv[w]; ri = swi[w]; }
            g_qidx[bh*NUMQ + s] = ri;
            s_best = ri;
        }
        __syncthreads();
        int ib = s_best;
        if ((ib & 255) == t) v[ib >> 8] = -INFINITY;
    }
}

// ---------------- attention: block per (b,h,group-of-4-q) ----------------
__global__ __launch_bounds__(256) void attn_kernel(float* __restrict__ out_attn) {
    int blk = blockIdx.x;
    int g = blk % 10;
    int h = (blk / 10) % Hh;
    int b = blk / (10 * Hh);
    __shared__ float qs[4][Dd];
    __shared__ float sc[4][Ll];
    __shared__ float red[8];
    __shared__ float pvs[4][4][Dd];
    __shared__ int qix[4];
    int tid = threadIdx.x;
    int lane = tid & 31, w = tid >> 5;
    if (tid < 4) qix[tid] = g_qidx[(b*Hh + h)*NUMQ + g*4 + tid];
    __syncthreads();
    {
        int qq = tid >> 6, d = tid & 63;
        qs[qq][d] = g_qp[((size_t)b*Ll + qix[qq])*DMM + h*Dd + d];
    }
    __syncthreads();
    const float scale = 0.125f;
    for (int j = w; j < Ll; j += 8) {
        const float2 kv = *(const float2*)&g_kp[((size_t)b*Ll + j)*DMM + h*Dd + lane*2];
        float p0 = kv.x*qs[0][lane*2] + kv.y*qs[0][lane*2+1];
        float p1 = kv.x*qs[1][lane*2] + kv.y*qs[1][lane*2+1];
        float p2 = kv.x*qs[2][lane*2] + kv.y*qs[2][lane*2+1];
        float p3 = kv.x*qs[3][lane*2] + kv.y*qs[3][lane*2+1];
#pragma unroll
        for (int o = 16; o; o >>= 1) {
            p0 += __shfl_xor_sync(0xffffffffu, p0, o);
            p1 += __shfl_xor_sync(0xffffffffu, p1, o);
            p2 += __shfl_xor_sync(0xffffffffu, p2, o);
            p3 += __shfl_xor_sync(0xffffffffu, p3, o);
        }
        if (lane == 0) {
            sc[0][j] = p0 * scale; sc[1][j] = p1 * scale;
            sc[2][j] = p2 * scale; sc[3][j] = p3 * scale;
        }
    }
    __syncthreads();
#pragma unroll
    for (int q = 0; q < 4; q++) {
        float m = -INFINITY;
        for (int j = tid; j < Ll; j += 256) m = fmaxf(m, sc[q][j]);
#pragma unroll
        for (int o = 16; o; o >>= 1) m = fmaxf(m, __shfl_xor_sync(0xffffffffu, m, o));
        if (lane == 0) red[w] = m;
        __syncthreads();
        m = fmaxf(fmaxf(fmaxf(red[0],red[1]),fmaxf(red[2],red[3])),
                  fmaxf(fmaxf(red[4],red[5]),fmaxf(red[6],red[7])));
        __syncthreads();
        float s = 0.f;
        for (int j = tid; j < Ll; j += 256) { float e = expf(sc[q][j] - m); sc[q][j] = e; s += e; }
#pragma unroll
        for (int o = 16; o; o >>= 1) s += __shfl_xor_sync(0xffffffffu, s, o);
        if (lane == 0) red[w] = s;
        __syncthreads();
        float inv = 1.0f / (red[0]+red[1]+red[2]+red[3]+red[4]+red[5]+red[6]+red[7]);
        size_t aoff = ((size_t)(b*Hh + h)*NUMQ + g*4 + q) * Ll;
        for (int j = tid; j < Ll; j += 256) {
            float p = sc[q][j] * inv;
            sc[q][j] = p;
            out_attn[aoff + j] = p;
        }
        __syncthreads();
    }
    int d = tid & 63, part = tid >> 6;
    float a0 = 0.f, a1 = 0.f, a2 = 0.f, a3 = 0.f;
    int j0 = part * 512;
    for (int j = j0; j < j0 + 512; j++) {
        float v = g_vp[((size_t)b*Ll + j)*DMM + h*Dd + d];
        a0 += sc[0][j]*v; a1 += sc[1][j]*v; a2 += sc[2][j]*v; a3 += sc[3][j]*v;
    }
    pvs[part][0][d] = a0; pvs[part][1][d] = a1;
    pvs[part][2][d] = a2; pvs[part][3][d] = a3;
    __syncthreads();
    if (part == 0) {
#pragma unroll
        for (int q = 0; q < 4; q++) {
            float r = pvs[0][q][d] + pvs[1][q][d] + pvs[2][q][d] + pvs[3][q][d];
            g_outsel[((size_t)((b*Hh + h)*NUMQ) + g*4 + q)*Dd + d] = r;
        }
    }
}

// ---------------- residual + layernorm (vmean/outsel compose) ----------------
__global__ __launch_bounds__(256) void ln_kernel(const float* __restrict__ qin,
                                                 const float* __restrict__ gamma,
                                                 const float* __restrict__ beta,
                                                 float* __restrict__ out)
{
    int row = blockIdx.x;            // Bb*Ll
    int b = row >> 11, l = row & (Ll - 1);
    int tid = threadIdx.x;
    __shared__ float sm[8], sm2[8];
    __shared__ int slots[8];
    if (tid < 8) slots[tid] = g_slot[(size_t)(b*Hh + tid)*Ll + l];
    __syncthreads();
    const float* qr = qin + (size_t)row * DMM;
    int c0 = tid, c1 = tid + 256;
    int h0 = c0 >> 6, h1 = c1 >> 6;
    int s0i = slots[h0], s1i = slots[h1];
    float ctx0 = (s0i >= 0)
        ? g_outsel[((size_t)((b*Hh + h0)*NUMQ) + s0i)*Dd + (c0 & 63)]
        : g_vmean[b*DMM + c0];
    float ctx1 = (s1i >= 0)
        ? g_outsel[((size_t)((b*Hh + h1)*NUMQ) + s1i)*Dd + (c1 & 63)]
        : g_vmean[b*DMM + c1];
    float v0 = ctx0 + qr[c0];
    float v1 = ctx1 + qr[c1];
    int lane = tid & 31, w = tid >> 5;
    float s = v0 + v1;
#pragma unroll
    for (int o = 16; o; o >>= 1) s += __shfl_xor_sync(0xffffffffu, s, o);
    if (lane == 0) sm[w] = s;
    __syncthreads();
    float mean = (sm[0]+sm[1]+sm[2]+sm[3]+sm[4]+sm[5]+sm[6]+sm[7]) * (1.0f / DMM);
    float d0 = v0 - mean, d1 = v1 - mean;
    float s2 = d0*d0 + d1*d1;
#pragma unroll
    for (int o = 16; o; o >>= 1) s2 += __shfl_xor_sync(0xffffffffu, s2, o);
    if (lane == 0) sm2[w] = s2;
    __syncthreads();
    float var = (sm2[0]+sm2[1]+sm2[2]+sm2[3]+sm2[4]+sm2[5]+sm2[6]+sm2[7]) * (1.0f / DMM);
    float invstd = rsqrtf(var + LN_EPS);
    out[(size_t)row*DMM + c0] = d0 * invstd * gamma[c0] + beta[c0];
    out[(size_t)row*DMM + c1] = d1 * invstd * gamma[c1] + beta[c1];
}

// ---------------- launch ----------------
extern "C" void kernel_launch(void* const* d_in, const int* in_sizes, int n_in,
                              void* d_out, int out_size)
{
    const float* q     = (const float*)d_in[0];
    const float* k     = (const float*)d_in[1];
    const float* v     = (const float*)d_in[2];
    const float* Wq    = (const float*)d_in[3];
    const float* bq    = (const float*)d_in[4];
    const float* Wk    = (const float*)d_in[5];
    const float* bk    = (const float*)d_in[6];
    const float* Wv    = (const float*)d_in[7];
    const float* bv    = (const float*)d_in[8];
    const float* gamma = (const float*)d_in[9];
    const float* beta  = (const float*)d_in[10];
    const int*   ridx  = (const int*)d_in[11];
    float* out      = (float*)d_out;
    float* out_attn = out + (size_t)Bb * Ll * DMM;

    static bool attr_set = false;
    if (!attr_set) {
        cudaFuncSetAttribute(gemm_tc_kernel,
                             cudaFuncAttributeMaxDynamicSharedMemorySize, GEMM_SMEM);
        attr_set = true;
    }

    asplit_kernel<<<dim3((Bb*Ll*DMM/4 + 255)/256, 1, 3), 256>>>(q, k, v);
    wsplit_t_kernel<<<dim3(16, 16, 3), dim3(32, 8)>>>(Wq, Wk, Wv);

    gemm_tc_kernel<<<dim3(4, 32, 3), 256, GEMM_SMEM>>>(bq, bk, bv);

    vmean_part_kernel<<<128, DMM>>>();
    vmean_reduce_kernel<<<Bb, DMM>>>();

    measure_kernel<<<(Bb * Ll) / 8, 256>>>(ridx);
    topk_kernel<<<Bb * Hh, 256>>>();

    slot_init_kernel<<<(Bb*Hh*Ll) / 256, 256>>>();
    slot_scatter_kernel<<<3, 256>>>();

    attn_kernel<<<Bb * Hh * 10, 256>>>(out_attn);

    ln_kernel<<<Bb * Ll, 256>>>(q, gamma, beta, out);
}

// round 6
// speedup vs baseline: 1.3756x; 1.3756x over previous
#include <cuda_runtime.h>
#include <cuda_bf16.h>
#include <math.h>
#include <stdint.h>

#define Bb 2
#define Ll 2048
#define DMM 512
#define Hh 8
#define Dd 64
#define NUMK 40
#define NUMQ 40
#define LN_EPS 1e-5f

// ---------------- scratch (static device globals; no allocs allowed) ----------------
__device__ __align__(256) float g_qp[Bb*Ll*DMM];
__device__ __align__(256) float g_kp[Bb*Ll*DMM];
__device__ __align__(256) float g_vp[Bb*Ll*DMM];
__device__ __align__(256) float g_measure[Bb*Hh*Ll];
__device__ __align__(256) float g_vpart[Bb*128*DMM];
__device__ __align__(256) float g_vmean[Bb*DMM];
__device__ __align__(256) int   g_qidx[Bb*Hh*NUMQ];
__device__ __align__(256) int   g_slot[Bb*Hh*Ll];
__device__ __align__(256) float g_outsel[Bb*Hh*NUMQ*Dd];
// W transposed + bf16 hi/lo split: [which][N][K]
__device__ __align__(256) __nv_bfloat16 g_Wth[3*DMM*DMM];
__device__ __align__(256) __nv_bfloat16 g_Wtl[3*DMM*DMM];

// ============================ helpers ============================
__device__ __forceinline__ uint32_t smem_u32(const void* p) {
    uint32_t a;
    asm("{ .reg .u64 t; cvta.to.shared.u64 t, %1; cvt.u32.u64 %0, t; }" : "=r"(a) : "l"(p));
    return a;
}
#define SWZ128(off) ((off) ^ (((off) >> 3) & 0x70))

#define STS128(addr, a, b, c, d) \
    asm volatile("st.shared.v4.b32 [%0], {%1, %2, %3, %4};" \
                 :: "r"(addr), "r"(a), "r"(b), "r"(c), "r"(d) : "memory")

__device__ __forceinline__ void ldsm4(uint32_t& r0, uint32_t& r1, uint32_t& r2, uint32_t& r3,
                                      uint32_t addr) {
    asm volatile("ldmatrix.sync.aligned.m8n8.x4.shared.b16 {%0,%1,%2,%3}, [%4];"
                 : "=r"(r0), "=r"(r1), "=r"(r2), "=r"(r3) : "r"(addr));
}
__device__ __forceinline__ void mma16816(float* c, const uint32_t* a, uint32_t b0, uint32_t b1) {
    asm volatile(
        "mma.sync.aligned.m16n8k16.row.col.f32.bf16.bf16.f32 "
        "{%0,%1,%2,%3}, {%4,%5,%6,%7}, {%8,%9}, {%0,%1,%2,%3};"
        : "+f"(c[0]), "+f"(c[1]), "+f"(c[2]), "+f"(c[3])
        : "r"(a[0]), "r"(a[1]), "r"(a[2]), "r"(a[3]), "r"(b0), "r"(b1));
}

__device__ __forceinline__ void split2(float a, float b, uint32_t& h, uint32_t& l) {
    __nv_bfloat16 ha = __float2bfloat16(a), hb = __float2bfloat16(b);
    __nv_bfloat16 la = __float2bfloat16(a - __bfloat162float(ha));
    __nv_bfloat16 lb = __float2bfloat16(b - __bfloat162float(hb));
    __nv_bfloat162 hh(ha, hb), ll(la, lb);
    h = *reinterpret_cast<uint32_t*>(&hh);
    l = *reinterpret_cast<uint32_t*>(&ll);
}

// ---------------- W transpose + bf16 split: Wt[n][k] = W[k][n] ----------------
__global__ void wsplit_t_kernel(const float* __restrict__ Wq,
                                const float* __restrict__ Wk,
                                const float* __restrict__ Wv)
{
    int which = blockIdx.z;
    const float* W = (which == 0) ? Wq : (which == 1) ? Wk : Wv;
    __nv_bfloat16* Th = g_Wth + (size_t)which * DMM * DMM;
    __nv_bfloat16* Tl = g_Wtl + (size_t)which * DMM * DMM;
    __shared__ float tile[32][33];
    int n0 = blockIdx.x * 32, k0 = blockIdx.y * 32;
    int x = threadIdx.x, y = threadIdx.y;   // 32 x 8
#pragma unroll
    for (int yy = 0; yy < 32; yy += 8)
        tile[y + yy][x] = W[(size_t)(k0 + y + yy) * DMM + n0 + x];
    __syncthreads();
#pragma unroll
    for (int yy = 0; yy < 32; yy += 8) {
        int n = n0 + y + yy;
        float f = tile[x][y + yy];           // = W[k0+x][n]
        __nv_bfloat16 h = __float2bfloat16(f);
        Th[(size_t)n * DMM + k0 + x] = h;
        Tl[(size_t)n * DMM + k0 + x] = __float2bfloat16(f - __bfloat162float(h));
    }
}

// ---------------- HMMA GEMM (R4 proven): C = A@W + bias, split fused in staging ----------------
#define OFF_AH 0
#define OFF_AL 16384
#define OFF_BH 32768
#define OFF_BL 49152

__global__ void __launch_bounds__(256, 1)
gemm_tc_kernel(const float* __restrict__ qin, const float* __restrict__ kin,
               const float* __restrict__ vin,
               const float* __restrict__ bq, const float* __restrict__ bk,
               const float* __restrict__ bv)
{
    extern __shared__ char dsm[];

    int which = blockIdx.z;
    const float* A    = (which == 0) ? qin : (which == 1) ? kin : vin;
    const float* bias = (which == 0) ? bq  : (which == 1) ? bk  : bv;
    float* C          = (which == 0) ? g_qp : (which == 1) ? g_kp : g_vp;
    const __nv_bfloat16* Bh = g_Wth + (size_t)which * DMM * DMM;
    const __nv_bfloat16* Bl = g_Wtl + (size_t)which * DMM * DMM;

    int tid = threadIdx.x, wid = tid >> 5, lane = tid & 31;
    int m0 = blockIdx.y * 128, n0 = blockIdx.x * 128;
    int wm = wid & 1, wn = wid >> 1;

    uint32_t sb = (smem_u32(dsm) + 1023u) & ~1023u;

    uint32_t soff[4];
    int rr[4], cc[4];
#pragma unroll
    for (int jj = 0; jj < 4; jj++) {
        int i = tid + 256 * jj;
        rr[jj] = i >> 3;
        cc[jj] = i & 7;
        soff[jj] = SWZ128((uint32_t)(rr[jj] * 128 + cc[jj] * 16));
    }

    uint32_t a_off[4], b_off[2];
#pragma unroll
    for (int mt = 0; mt < 4; mt++)
        a_off[mt] = (uint32_t)((wm * 64 + mt * 16 + (lane & 15)) * 128);
#pragma unroll
    for (int bt = 0; bt < 2; bt++)
        b_off[bt] = (uint32_t)((wn * 32 + bt * 16 + (lane & 15)) * 128);
    int lhalf = lane >> 4;

    float acc[4][4][4];
#pragma unroll
    for (int i = 0; i < 4; i++)
#pragma unroll
        for (int j = 0; j < 4; j++)
#pragma unroll
            for (int c = 0; c < 4; c++) acc[i][j][c] = 0.f;

    float4 fa[8];
    uint4 vbh[4], vbl[4];

#pragma unroll
    for (int jj = 0; jj < 4; jj++) {
        const float* pa = A + (size_t)(m0 + rr[jj]) * DMM + cc[jj] * 8;
        fa[2*jj]   = *(const float4*)pa;
        fa[2*jj+1] = *(const float4*)(pa + 4);
        vbh[jj] = *(const uint4*)(Bh + (size_t)(n0 + rr[jj]) * DMM + cc[jj] * 8);
        vbl[jj] = *(const uint4*)(Bl + (size_t)(n0 + rr[jj]) * DMM + cc[jj] * 8);
    }

    for (int kt = 0; kt < 8; kt++) {
#pragma unroll
        for (int jj = 0; jj < 4; jj++) {
            uint32_t h0,h1,h2,h3,l0,l1,l2,l3;
            split2(fa[2*jj].x,   fa[2*jj].y,   h0, l0);
            split2(fa[2*jj].z,   fa[2*jj].w,   h1, l1);
            split2(fa[2*jj+1].x, fa[2*jj+1].y, h2, l2);
            split2(fa[2*jj+1].z, fa[2*jj+1].w, h3, l3);
            STS128(sb + OFF_AH + soff[jj], h0, h1, h2, h3);
            STS128(sb + OFF_AL + soff[jj], l0, l1, l2, l3);
            STS128(sb + OFF_BH + soff[jj], vbh[jj].x, vbh[jj].y, vbh[jj].z, vbh[jj].w);
            STS128(sb + OFF_BL + soff[jj], vbl[jj].x, vbl[jj].y, vbl[jj].z, vbl[jj].w);
        }
        __syncthreads();

        if (kt < 7) {
            int kb = (kt + 1) * 64;
#pragma unroll
            for (int jj = 0; jj < 4; jj++) {
                const float* pa = A + (size_t)(m0 + rr[jj]) * DMM + kb + cc[jj] * 8;
                fa[2*jj]   = *(const float4*)pa;
                fa[2*jj+1] = *(const float4*)(pa + 4);
                vbh[jj] = *(const uint4*)(Bh + (size_t)(n0 + rr[jj]) * DMM + kb + cc[jj] * 8);
                vbl[jj] = *(const uint4*)(Bl + (size_t)(n0 + rr[jj]) * DMM + kb + cc[jj] * 8);
            }
        }

#pragma unroll
        for (int ks = 0; ks < 4; ks++) {
            uint32_t chunk = (uint32_t)((2*ks + lhalf) * 16);
            uint32_t ah[4][4], al[4][4];
#pragma unroll
            for (int mt = 0; mt < 4; mt++) {
                uint32_t sw = SWZ128(a_off[mt] + chunk);
                ldsm4(ah[mt][0], ah[mt][1], ah[mt][2], ah[mt][3], sb + OFF_AH + sw);
                ldsm4(al[mt][0], al[mt][1], al[mt][2], al[mt][3], sb + OFF_AL + sw);
            }
            uint32_t bh[2][4], bl[2][4];
#pragma unroll
            for (int bt = 0; bt < 2; bt++) {
                uint32_t sw = SWZ128(b_off[bt] + chunk);
                ldsm4(bh[bt][0], bh[bt][1], bh[bt][2], bh[bt][3], sb + OFF_BH + sw);
                ldsm4(bl[bt][0], bl[bt][1], bl[bt][2], bl[bt][3], sb + OFF_BL + sw);
            }
#pragma unroll
            for (int mt = 0; mt < 4; mt++) {
#pragma unroll
                for (int nt = 0; nt < 4; nt++) {
                    int bt = nt >> 1, hi = nt & 1;
                    uint32_t bh0 = bh[bt][hi],   bh1 = bh[bt][hi+2];
                    uint32_t bl0 = bl[bt][hi],   bl1 = bl[bt][hi+2];
                    mma16816(acc[mt][nt], ah[mt], bh0, bh1);
                    mma16816(acc[mt][nt], ah[mt], bl0, bl1);
                    mma16816(acc[mt][nt], al[mt], bh0, bh1);
                }
            }
        }
        __syncthreads();
    }

#pragma unroll
    for (int mt = 0; mt < 4; mt++) {
        int mrow = m0 + wm*64 + mt*16 + (lane >> 2);
#pragma unroll
        for (int nt = 0; nt < 4; nt++) {
            int ncol = n0 + wn*32 + nt*8 + (lane & 3)*2;
            float b0 = bias[ncol], b1 = bias[ncol + 1];
            float2 v0 = make_float2(acc[mt][nt][0] + b0, acc[mt][nt][1] + b1);
            float2 v1 = make_float2(acc[mt][nt][2] + b0, acc[mt][nt][3] + b1);
            *(float2*)(C + (size_t)mrow * DMM + ncol)       = v0;
            *(float2*)(C + (size_t)(mrow + 8) * DMM + ncol) = v1;
        }
    }
}

// ---------------- v_mean (two-stage, deterministic) ----------------
__global__ void vmean_part_kernel() {
    int blk = blockIdx.x;               // 256
    int b = blk >> 7, j = blk & 127;    // 16 rows each
    int c = threadIdx.x;                // 512
    int base = j * 16;
    const float* p = &g_vp[((size_t)b*Ll + base)*DMM + c];
    float s0 = 0.f, s1 = 0.f, s2 = 0.f, s3 = 0.f;
#pragma unroll
    for (int l = 0; l < 16; l += 4) {
        s0 += p[(size_t)(l  )*DMM];
        s1 += p[(size_t)(l+1)*DMM];
        s2 += p[(size_t)(l+2)*DMM];
        s3 += p[(size_t)(l+3)*DMM];
    }
    g_vpart[(size_t)blk*DMM + c] = (s0 + s1) + (s2 + s3);
}
__global__ void vmean_reduce_kernel() {
    int b = blockIdx.x; int c = threadIdx.x;
    float s0 = 0.f, s1 = 0.f, s2 = 0.f, s3 = 0.f;
#pragma unroll 8
    for (int j = 0; j < 128; j += 4) {
        s0 += g_vpart[((size_t)b*128 + j    )*DMM + c];
        s1 += g_vpart[((size_t)b*128 + j + 1)*DMM + c];
        s2 += g_vpart[((size_t)b*128 + j + 2)*DMM + c];
        s3 += g_vpart[((size_t)b*128 + j + 3)*DMM + c];
    }
    g_vmean[b*DMM + c] = ((s0 + s1) + (s2 + s3)) * (1.0f / Ll);
}

// ---------------- slot init (also positions measure as the 6th launch for ncu) ----------------
__global__ void slot_init_kernel() {
    int i = blockIdx.x * blockDim.x + threadIdx.x;
    g_slot[i] = -1;
}

// ---------------- pre + measure: one warp per (b,l), all 8 heads ----------------
__global__ __launch_bounds__(256) void measure_kernel(const int* __restrict__ ridx) {
    int gw = (blockIdx.x * blockDim.x + threadIdx.x) >> 5;   // 0..4095
    int lane = threadIdx.x & 31;
    if (gw >= Bb * Ll) return;
    int l = gw & (Ll - 1);
    int b = gw >> 11;
    const float4* qrow = (const float4*)&g_qp[((size_t)b*Ll + l) * DMM];
    float4 q0 = qrow[lane*4+0], q1 = qrow[lane*4+1], q2 = qrow[lane*4+2], q3 = qrow[lane*4+3];
    int i0 = ridx[l*NUMK + lane];
    int i1 = ridx[l*NUMK + 32 + (lane & 7)];
    float mx = -INFINITY, sm = 0.f;
#pragma unroll 4
    for (int j = 0; j < NUMK; j++) {
        int ki = (j < 32) ? __shfl_sync(0xffffffffu, i0, j)
                          : __shfl_sync(0xffffffffu, i1, j - 32);
        const float4* kr = (const float4*)&g_kp[((size_t)b*Ll + ki) * DMM];
        float4 k0 = kr[lane*4+0], k1 = kr[lane*4+1], k2 = kr[lane*4+2], k3 = kr[lane*4+3];
        float p = q0.x*k0.x + q0.y*k0.y + q0.z*k0.z + q0.w*k0.w
                + q1.x*k1.x + q1.y*k1.y + q1.z*k1.z + q1.w*k1.w
                + q2.x*k2.x + q2.y*k2.y + q2.z*k2.z + q2.w*k2.w
                + q3.x*k3.x + q3.y*k3.y + q3.z*k3.z + q3.w*k3.w;
        p += __shfl_xor_sync(0xffffffffu, p, 1);
        p += __shfl_xor_sync(0xffffffffu, p, 2);
        mx = fmaxf(mx, p);
        sm += p;
    }
    if ((lane & 3) == 0) {
        int h = lane >> 2;
        g_measure[((size_t)b*Hh + h)*Ll + l] = mx - sm * (1.0f / Ll);
    }
}

// ---------------- exact top-40 per (b,h), register-resident + slot scatter ----------------
__global__ __launch_bounds__(256) void topk_kernel() {
    int bh = blockIdx.x, t = threadIdx.x;
    float v[8];
    const float* src = g_measure + (size_t)bh * Ll;
#pragma unroll
    for (int m = 0; m < 8; m++) v[m] = src[t + 256*m];
    __shared__ float swv[8];
    __shared__ int   swi[8];
    __shared__ int   s_best;
    __shared__ int   qsel[NUMQ];
    for (int s = 0; s < NUMQ; s++) {
        float bv = v[0]; int bi = t;
#pragma unroll
        for (int m = 1; m < 8; m++) {
            int i = t + 256*m;
            if (v[m] > bv || (v[m] == bv && i < bi)) { bv = v[m]; bi = i; }
        }
#pragma unroll
        for (int o = 16; o; o >>= 1) {
            float ov = __shfl_xor_sync(0xffffffffu, bv, o);
            int   oi = __shfl_xor_sync(0xffffffffu, bi, o);
            if (ov > bv || (ov == bv && oi < bi)) { bv = ov; bi = oi; }
        }
        if ((t & 31) == 0) { swv[t >> 5] = bv; swi[t >> 5] = bi; }
        __syncthreads();
        if (t == 0) {
            float rv = swv[0]; int ri = swi[0];
#pragma unroll
            for (int w = 1; w < 8; w++)
                if (swv[w] > rv || (swv[w] == rv && swi[w] < ri)) { rv = swv[w]; ri = swi[w]; }
            g_qidx[bh*NUMQ + s] = ri;
            qsel[s] = ri;
            s_best = ri;
        }
        __syncthreads();
        int ib = s_best;
        if ((ib & 255) == t) v[ib >> 8] = -INFINITY;
    }
    if (t < NUMQ) g_slot[(size_t)bh * Ll + qsel[t]] = t;
}

// ---------------- attention: block per (b,h,group-of-4-q), lane-quad scores ----------------
__global__ __launch_bounds__(256) void attn_kernel(float* __restrict__ out_attn) {
    int blk = blockIdx.x;
    int g = blk % 10;
    int h = (blk / 10) % Hh;
    int b = blk / (10 * Hh);
    __shared__ float qs[4][Dd];
    __shared__ float sc[4][Ll];
    __shared__ float red[8];
    __shared__ float pvs[4][4][Dd];
    __shared__ int qix[4];
    int tid = threadIdx.x;
    int lane = tid & 31, w = tid >> 5;
    if (tid < 4) qix[tid] = g_qidx[(b*Hh + h)*NUMQ + g*4 + tid];
    __syncthreads();
    {
        int qq = tid >> 6, d = tid & 63;
        qs[qq][d] = g_qp[((size_t)b*Ll + qix[qq])*DMM + h*Dd + d];
    }
    __syncthreads();
    const float scale = 0.125f;

    // lane-quad scores: 4 lanes per key, q-quad in registers
    int quarter = lane & 3, keyoff = lane >> 2;   // key-in-pass 0..7
    float4 qr[4][4];
#pragma unroll
    for (int q = 0; q < 4; q++)
#pragma unroll
        for (int c = 0; c < 4; c++)
            qr[q][c] = *(float4*)&qs[q][quarter*16 + c*4];

    for (int pass = 0; pass < 32; pass++) {
        int j = w*256 + pass*8 + keyoff;
        const float4* kr = (const float4*)&g_kp[((size_t)b*Ll + j)*DMM + h*Dd + quarter*16];
        float4 k0 = kr[0], k1 = kr[1], k2 = kr[2], k3 = kr[3];
        float p[4];
#pragma unroll
        for (int q = 0; q < 4; q++) {
            p[q] = qr[q][0].x*k0.x + qr[q][0].y*k0.y + qr[q][0].z*k0.z + qr[q][0].w*k0.w
                 + qr[q][1].x*k1.x + qr[q][1].y*k1.y + qr[q][1].z*k1.z + qr[q][1].w*k1.w
                 + qr[q][2].x*k2.x + qr[q][2].y*k2.y + qr[q][2].z*k2.z + qr[q][2].w*k2.w
                 + qr[q][3].x*k3.x + qr[q][3].y*k3.y + qr[q][3].z*k3.z + qr[q][3].w*k3.w;
            p[q] += __shfl_xor_sync(0xffffffffu, p[q], 1);
            p[q] += __shfl_xor_sync(0xffffffffu, p[q], 2);
        }
        if (quarter == 0) {
            sc[0][j] = p[0] * scale; sc[1][j] = p[1] * scale;
            sc[2][j] = p[2] * scale; sc[3][j] = p[3] * scale;
        }
    }
    __syncthreads();
#pragma unroll
    for (int q = 0; q < 4; q++) {
        float m = -INFINITY;
        for (int j = tid; j < Ll; j += 256) m = fmaxf(m, sc[q][j]);
#pragma unroll
        for (int o = 16; o; o >>= 1) m = fmaxf(m, __shfl_xor_sync(0xffffffffu, m, o));
        if (lane == 0) red[w] = m;
        __syncthreads();
        m = fmaxf(fmaxf(fmaxf(red[0],red[1]),fmaxf(red[2],red[3])),
                  fmaxf(fmaxf(red[4],red[5]),fmaxf(red[6],red[7])));
        __syncthreads();
        float s = 0.f;
        for (int j = tid; j < Ll; j += 256) { float e = expf(sc[q][j] - m); sc[q][j] = e; s += e; }
#pragma unroll
        for (int o = 16; o; o >>= 1) s += __shfl_xor_sync(0xffffffffu, s, o);
        if (lane == 0) red[w] = s;
        __syncthreads();
        float inv = 1.0f / (red[0]+red[1]+red[2]+red[3]+red[4]+red[5]+red[6]+red[7]);
        size_t aoff = ((size_t)(b*Hh + h)*NUMQ + g*4 + q) * Ll;
        for (int j = tid; j < Ll; j += 256) {
            float p = sc[q][j] * inv;
            sc[q][j] = p;
            out_attn[aoff + j] = p;
        }
        __syncthreads();
    }
    int d = tid & 63, part = tid >> 6;
    float a0 = 0.f, a1 = 0.f, a2 = 0.f, a3 = 0.f;
    int j0 = part * 512;
    for (int j = j0; j < j0 + 512; j++) {
        float vv = g_vp[((size_t)b*Ll + j)*DMM + h*Dd + d];
        a0 += sc[0][j]*vv; a1 += sc[1][j]*vv; a2 += sc[2][j]*vv; a3 += sc[3][j]*vv;
    }
    pvs[part][0][d] = a0; pvs[part][1][d] = a1;
    pvs[part][2][d] = a2; pvs[part][3][d] = a3;
    __syncthreads();
    if (part == 0) {
#pragma unroll
        for (int q = 0; q < 4; q++) {
            float r = pvs[0][q][d] + pvs[1][q][d] + pvs[2][q][d] + pvs[3][q][d];
            g_outsel[((size_t)((b*Hh + h)*NUMQ) + g*4 + q)*Dd + d] = r;
        }
    }
}

// ---------------- residual + layernorm (vmean/outsel compose) ----------------
__global__ __launch_bounds__(256) void ln_kernel(const float* __restrict__ qin,
                                                 const float* __restrict__ gamma,
                                                 const float* __restrict__ beta,
                                                 float* __restrict__ out)
{
    int row = blockIdx.x;            // Bb*Ll
    int b = row >> 11, l = row & (Ll - 1);
    int tid = threadIdx.x;
    __shared__ float sm[8], sm2[8];
    __shared__ int slots[8];
    if (tid < 8) slots[tid] = g_slot[(size_t)(b*Hh + tid)*Ll + l];
    __syncthreads();
    const float* qr = qin + (size_t)row * DMM;
    int c0 = tid, c1 = tid + 256;
    int h0 = c0 >> 6, h1 = c1 >> 6;
    int s0i = slots[h0], s1i = slots[h1];
    float ctx0 = (s0i >= 0)
        ? g_outsel[((size_t)((b*Hh + h0)*NUMQ) + s0i)*Dd + (c0 & 63)]
        : g_vmean[b*DMM + c0];
    float ctx1 = (s1i >= 0)
        ? g_outsel[((size_t)((b*Hh + h1)*NUMQ) + s1i)*Dd + (c1 & 63)]
        : g_vmean[b*DMM + c1];
    float v0 = ctx0 + qr[c0];
    float v1 = ctx1 + qr[c1];
    int lane = tid & 31, w = tid >> 5;
    float s = v0 + v1;
#pragma unroll
    for (int o = 16; o; o >>= 1) s += __shfl_xor_sync(0xffffffffu, s, o);
    if (lane == 0) sm[w] = s;
    __syncthreads();
    float mean = (sm[0]+sm[1]+sm[2]+sm[3]+sm[4]+sm[5]+sm[6]+sm[7]) * (1.0f / DMM);
    float d0 = v0 - mean, d1 = v1 - mean;
    float s2 = d0*d0 + d1*d1;
#pragma unroll
    for (int o = 16; o; o >>= 1) s2 += __shfl_xor_sync(0xffffffffu, s2, o);
    if (lane == 0) sm2[w] = s2;
    __syncthreads();
    float var = (sm2[0]+sm2[1]+sm2[2]+sm2[3]+sm2[4]+sm2[5]+sm2[6]+sm2[7]) * (1.0f / DMM);
    float invstd = rsqrtf(var + LN_EPS);
    out[(size_t)row*DMM + c0] = d0 * invstd * gamma[c0] + beta[c0];
    out[(size_t)row*DMM + c1] = d1 * invstd * gamma[c1] + beta[c1];
}

// ---------------- launch ----------------
extern "C" void kernel_launch(void* const* d_in, const int* in_sizes, int n_in,
                              void* d_out, int out_size)
{
    const float* q     = (const float*)d_in[0];
    const float* k     = (const float*)d_in[1];
    const float* v     = (const float*)d_in[2];
    const float* Wq    = (const float*)d_in[3];
    const float* bq    = (const float*)d_in[4];
    const float* Wk    = (const float*)d_in[5];
    const float* bk    = (const float*)d_in[6];
    const float* Wv    = (const float*)d_in[7];
    const float* bv    = (const float*)d_in[8];
    const float* gamma = (const float*)d_in[9];
    const float* beta  = (const float*)d_in[10];
    const int*   ridx  = (const int*)d_in[11];
    float* out      = (float*)d_out;
    float* out_attn = out + (size_t)Bb * Ll * DMM;

    static bool attr_set = false;
    if (!attr_set) {
        cudaFuncSetAttribute(gemm_tc_kernel,
                             cudaFuncAttributeMaxDynamicSharedMemorySize, 66560);
        attr_set = true;
    }

    // launch order chosen so ncu (-s 5 -c 1) profiles measure_kernel (6th launch)
    wsplit_t_kernel<<<dim3(16, 16, 3), dim3(32, 8)>>>(Wq, Wk, Wv);       // 1
    gemm_tc_kernel<<<dim3(4, 32, 3), 256, 66560>>>(q, k, v, bq, bk, bv); // 2
    vmean_part_kernel<<<256, DMM>>>();                                    // 3
    vmean_reduce_kernel<<<Bb, DMM>>>();                                   // 4
    slot_init_kernel<<<(Bb*Hh*Ll) / 256, 256>>>();                        // 5
    measure_kernel<<<(Bb * Ll) / 8, 256>>>(ridx);                         // 6 <- profiled
    topk_kernel<<<Bb * Hh, 256>>>();                                      // 7
    attn_kernel<<<Bb * Hh * 10, 256>>>(out_attn);                         // 8
    ln_kernel<<<Bb * Ll, 256>>>(q, gamma, beta, out);                     // 9
}